// round 1
// baseline (speedup 1.0000x reference)
#include <cuda_runtime.h>
#include <cuda_bf16.h>
#include <cstdint>

// out = x @ V @ diag(S) @ U^T + bias
//   GEMM1 (NN): T[8192,1024] = x[8192,4096] @ V[4096,1024], epilogue *S[n]
//   GEMM2 (NT): out[8192,4096] = T[8192,1024] @ U[4096,1024]^T, epilogue +bias[n]

#define BM 128
#define BN 128
#define BK 16
#define TM 8
#define TN 8

// 32 MB scratch for the rank-space intermediate (allocation-free rule: __device__ global)
__device__ float g_scratch[8192 * 1024];

// BT: B is [N,K] row-major (use transposed access). SCALE: c *= E[n]. BIAS: c += E[n].
template <bool BT, bool SCALE, bool BIAS>
__global__ __launch_bounds__(256, 2) void sgemm_kernel(
    const float* __restrict__ A, const float* __restrict__ B,
    const float* __restrict__ E, float* __restrict__ C,
    int M, int N, int K)
{
    __shared__ float As[BK][BM];
    __shared__ float Bs[BK][BN];

    const int tid = threadIdx.x;
    const int bm = blockIdx.y * BM;
    const int bn = blockIdx.x * BN;

    const int ty = (tid / 16) * TM;   // 0..120
    const int tx = (tid % 16) * TN;   // 0..120

    // A-tile loader mapping: 256 threads cover 64 rows x 16 cols per pass (2 passes)
    const int a_row = tid >> 2;          // 0..63
    const int a_col = (tid & 3) * 4;     // 0,4,8,12
    // B-tile loader mapping (NN): 8 k-rows x 128 n-cols per pass (2 passes)
    const int b_row = tid >> 5;          // 0..7
    const int b_col = (tid & 31) * 4;    // 0..124

    float acc[TM][TN];
    #pragma unroll
    for (int i = 0; i < TM; i++)
        #pragma unroll
        for (int j = 0; j < TN; j++)
            acc[i][j] = 0.0f;

    for (int k0 = 0; k0 < K; k0 += BK) {
        // ---- stage A tile (transposed into As[k][m]) ----
        #pragma unroll
        for (int p = 0; p < 2; p++) {
            int r = a_row + p * 64;
            float4 v = *reinterpret_cast<const float4*>(
                &A[(size_t)(bm + r) * K + k0 + a_col]);
            As[a_col + 0][r] = v.x;
            As[a_col + 1][r] = v.y;
            As[a_col + 2][r] = v.z;
            As[a_col + 3][r] = v.w;
        }
        // ---- stage B tile into Bs[k][n] ----
        if (BT) {
            // B is [N,K] row-major: Bs[k][n] = B[(bn+n)*K + k0+k]
            #pragma unroll
            for (int p = 0; p < 2; p++) {
                int r = a_row + p * 64;  // n within tile
                float4 v = *reinterpret_cast<const float4*>(
                    &B[(size_t)(bn + r) * K + k0 + a_col]);
                Bs[a_col + 0][r] = v.x;
                Bs[a_col + 1][r] = v.y;
                Bs[a_col + 2][r] = v.z;
                Bs[a_col + 3][r] = v.w;
            }
        } else {
            // B is [K,N] row-major: Bs[k][n] = B[(k0+k)*N + bn+n]
            #pragma unroll
            for (int p = 0; p < 2; p++) {
                int r = b_row + p * 8;
                float4 v = *reinterpret_cast<const float4*>(
                    &B[(size_t)(k0 + r) * N + bn + b_col]);
                *reinterpret_cast<float4*>(&Bs[r][b_col]) = v;
            }
        }
        __syncthreads();

        // ---- compute 8x8 microtile ----
        #pragma unroll
        for (int kk = 0; kk < BK; kk++) {
            float a[TM], b[TN];
            *reinterpret_cast<float4*>(&a[0]) = *reinterpret_cast<float4*>(&As[kk][ty]);
            *reinterpret_cast<float4*>(&a[4]) = *reinterpret_cast<float4*>(&As[kk][ty + 4]);
            *reinterpret_cast<float4*>(&b[0]) = *reinterpret_cast<float4*>(&Bs[kk][tx]);
            *reinterpret_cast<float4*>(&b[4]) = *reinterpret_cast<float4*>(&Bs[kk][tx + 4]);
            #pragma unroll
            for (int i = 0; i < TM; i++)
                #pragma unroll
                for (int j = 0; j < TN; j++)
                    acc[i][j] = fmaf(a[i], b[j], acc[i][j]);
        }
        __syncthreads();
    }

    // ---- epilogue ----
    #pragma unroll
    for (int i = 0; i < TM; i++) {
        const size_t row = (size_t)(bm + ty + i);
        #pragma unroll
        for (int j = 0; j < TN; j += 4) {
            int col = bn + tx + j;
            float4 v;
            v.x = acc[i][j + 0];
            v.y = acc[i][j + 1];
            v.z = acc[i][j + 2];
            v.w = acc[i][j + 3];
            if (SCALE) {
                v.x *= E[col + 0]; v.y *= E[col + 1];
                v.z *= E[col + 2]; v.w *= E[col + 3];
            }
            if (BIAS) {
                v.x += E[col + 0]; v.y += E[col + 1];
                v.z += E[col + 2]; v.w += E[col + 3];
            }
            *reinterpret_cast<float4*>(&C[row * N + col]) = v;
        }
    }
}

extern "C" void kernel_launch(void* const* d_in, const int* in_sizes, int n_in,
                              void* d_out, int out_size)
{
    const float* x    = (const float*)d_in[0];   // [4,2048,4096] = [8192,4096]
    const float* U    = (const float*)d_in[1];   // [4096,1024]
    const float* S    = (const float*)d_in[2];   // [1024]
    const float* V    = (const float*)d_in[3];   // [4096,1024]
    const float* bias = (const float*)d_in[4];   // [4096]
    float* out = (float*)d_out;                  // [8192,4096]

    float* scratch = nullptr;
    cudaGetSymbolAddress((void**)&scratch, g_scratch);

    const int M = 8192;
    const int RANK = 1024;
    const int H = 4096;

    // GEMM1: T = x @ V, scaled by S
    {
        dim3 grid(RANK / BN, M / BM);  // (8, 64)
        sgemm_kernel<false, true, false><<<grid, 256>>>(x, V, S, scratch, M, RANK, H);
    }
    // GEMM2: out = T @ U^T + bias
    {
        dim3 grid(H / BN, M / BM);     // (32, 64)
        sgemm_kernel<true, false, true><<<grid, 256>>>(scratch, U, bias, out, M, H, RANK);
    }
}

// round 3
// speedup vs baseline: 3.2731x; 3.2731x over previous
#include <cuda_runtime.h>
#include <cstdint>

// out = x @ V @ diag(S) @ U^T + bias  via legacy tensor-core mma.sync tf32.
// (tcgen05 is unusable here: harness compiles PTX at .target sm_103 (no 'a'),
//  and ptxas rejects all tcgen05/TMEM ops. mma.sync m16n8k8 tf32 is baseline PTX.)
//
// GEMM1 (NT): Ts[8192,1024] = x[8192,4096] @ Vt[1024,4096]^T, Vt = (V*S)^T (prep)
// GEMM2 (NT): out[8192,4096] = Ts[8192,1024] @ U[4096,1024]^T + bias

#define CTA_M 128
#define CTA_N 128
#define CTA_K 32

// Fragment-ordered smem blocks, padded to dodge STS bank conflicts.
// A block (one 16x8-k tf32 tile): 32 lanes * 16B = 512 -> pad 528.
// B block (one 8x8-k tile):       32 lanes * 8B  = 256 -> pad 272.
static constexpr int A_BLK = 528;
static constexpr int B_BLK = 272;
static constexpr int A_STAGE = 8 * 4 * A_BLK;   // 8 mtiles * 4 ktiles = 16896 B
static constexpr int B_STAGE = 16 * 4 * B_BLK;  // 16 ntiles * 4 ktiles = 17408 B
static constexpr int SMEM_TOTAL = 2 * A_STAGE + 2 * B_STAGE;  // 68608 B

// Scratch (allocation-free rule: __device__ globals)
__device__ __align__(128) float g_Vt[1024 * 4096];  // (V*S)^T : [rank][4096]
__device__ __align__(128) float g_Ts[8192 * 1024];  // x @ (V*S) : [8192][rank]

__device__ __forceinline__ uint32_t f2tf32(float v) {
    uint32_t u;
    asm("cvt.rna.tf32.f32 %0, %1;" : "=r"(u) : "f"(v));
    return u;
}

__device__ __forceinline__ void mma_tf32(float& d0, float& d1, float& d2, float& d3,
                                         uint32_t a0, uint32_t a1, uint32_t a2, uint32_t a3,
                                         uint32_t b0, uint32_t b1) {
    asm volatile(
        "mma.sync.aligned.m16n8k8.row.col.f32.tf32.tf32.f32 "
        "{%0,%1,%2,%3}, {%4,%5,%6,%7}, {%8,%9}, {%0,%1,%2,%3};"
        : "+f"(d0), "+f"(d1), "+f"(d2), "+f"(d3)
        : "r"(a0), "r"(a1), "r"(a2), "r"(a3), "r"(b0), "r"(b1));
}

// ---------------- prep: Vt[n][k] = V[k][n] * S[n] ----------------
__global__ void prep_vt(const float* __restrict__ V, const float* __restrict__ S,
                        float* __restrict__ Vt) {
    __shared__ float t[32][33];
    int k0 = blockIdx.x * 32;   // over 4096
    int n0 = blockIdx.y * 32;   // over 1024
    int tx = threadIdx.x, ty = threadIdx.y;
    #pragma unroll
    for (int r = ty; r < 32; r += 8)
        t[r][tx] = V[(size_t)(k0 + r) * 1024 + n0 + tx];
    __syncthreads();
    #pragma unroll
    for (int r = ty; r < 32; r += 8) {
        int n = n0 + r, k = k0 + tx;
        Vt[(size_t)n * 4096 + k] = t[tx][r] * S[n];
    }
}

// ---------------- main NT GEMM: C[M,N] = A[M,K] @ B[N,K]^T (+bias) ----------------
template <bool HAS_BIAS>
__global__ __launch_bounds__(256) void tf32_gemm_nt(
    const float* __restrict__ A, const float* __restrict__ B,
    const float* __restrict__ bias, float* __restrict__ C,
    int K, int lda, int ldb, int ldc)
{
    extern __shared__ char sm[];
    const int tid = threadIdx.x;
    const int bm = blockIdx.y * CTA_M;
    const int bn = blockIdx.x * CTA_N;

    // warp layout: 2 (m) x 4 (n); warp tile 64x32
    const int wid = tid >> 5, lane = tid & 31;
    const int wm = wid >> 2, wn = wid & 3;

    // ---- loader decomposition (per thread, constant across j) ----
    // float4 index i = tid + 256*j ; row = i>>3 (+32 per j), t = i&7
    const int t_ = tid & 7;
    const int row0 = tid >> 3;             // 0..31
    const int c0 = t_ * 4;                 // k offset of the float4 within CTA_K
    // A side
    const int rA = row0 & 15;
    const int ktile = t_ >> 1;
    const int regA = ((rA >> 3) & 1) + ((t_ & 1) << 1);
    const int laneA = (rA & 7) * 4;
    const int mt0 = row0 >> 4;             // 0 or 1; +2 per j
    // B side
    const int gB = row0 & 7;
    const int regB = t_ & 1;
    const int nt0 = row0 >> 3;             // 0..3; +4 per j

    auto As = [&](int p) { return p * A_STAGE; };
    auto Bs = [&](int p) { return 2 * A_STAGE + p * B_STAGE; };

    float4 va[4], vb[4];

    auto ldg = [&](int kc) {
        const int k0 = kc * CTA_K + c0;
        #pragma unroll
        for (int j = 0; j < 4; j++) {
            va[j] = *reinterpret_cast<const float4*>(A + (size_t)(bm + row0 + 32 * j) * lda + k0);
            vb[j] = *reinterpret_cast<const float4*>(B + (size_t)(bn + row0 + 32 * j) * ldb + k0);
        }
    };

    auto sts = [&](int p) {
        #pragma unroll
        for (int j = 0; j < 4; j++) {
            const float* pa = &va[j].x;
            const float* pb = &vb[j].x;
            int ablk = As(p) + ((mt0 + 2 * j) * 4 + ktile) * A_BLK;
            int bblk = Bs(p) + ((nt0 + 4 * j) * 4 + ktile) * B_BLK;
            #pragma unroll
            for (int e = 0; e < 4; e++) {
                *reinterpret_cast<uint32_t*>(sm + ablk + (laneA + e) * 16 + regA * 4) = f2tf32(pa[e]);
                *reinterpret_cast<uint32_t*>(sm + bblk + (gB * 4 + e) * 8 + regB * 4) = f2tf32(pb[e]);
            }
        }
    };

    float acc[4][4][4];
    #pragma unroll
    for (int i = 0; i < 4; i++)
        #pragma unroll
        for (int j = 0; j < 4; j++)
            #pragma unroll
            for (int r = 0; r < 4; r++)
                acc[i][j][r] = 0.0f;

    const int T = K / CTA_K;
    ldg(0);
    sts(0);
    __syncthreads();

    for (int tc = 0; tc < T; ++tc) {
        const int p = tc & 1;
        if (tc + 1 < T) ldg(tc + 1);

        #pragma unroll
        for (int ks = 0; ks < 4; ks++) {
            uint4 af[4];
            uint2 bf[4];
            #pragma unroll
            for (int mt = 0; mt < 4; mt++)
                af[mt] = *reinterpret_cast<const uint4*>(
                    sm + As(p) + ((wm * 4 + mt) * 4 + ks) * A_BLK + lane * 16);
            #pragma unroll
            for (int nt = 0; nt < 4; nt++)
                bf[nt] = *reinterpret_cast<const uint2*>(
                    sm + Bs(p) + ((wn * 4 + nt) * 4 + ks) * B_BLK + lane * 8);
            #pragma unroll
            for (int mt = 0; mt < 4; mt++)
                #pragma unroll
                for (int nt = 0; nt < 4; nt++)
                    mma_tf32(acc[mt][nt][0], acc[mt][nt][1], acc[mt][nt][2], acc[mt][nt][3],
                             af[mt].x, af[mt].y, af[mt].z, af[mt].w,
                             bf[nt].x, bf[nt].y);
        }

        if (tc + 1 < T) sts((tc + 1) & 1);
        __syncthreads();
    }

    // ---- epilogue ----
    const int g = lane >> 2, tig = lane & 3;
    #pragma unroll
    for (int mt = 0; mt < 4; mt++) {
        #pragma unroll
        for (int nt = 0; nt < 4; nt++) {
            int row = bm + wm * 64 + mt * 16 + g;
            int col = bn + wn * 32 + nt * 8 + tig * 2;
            float2 v0 = make_float2(acc[mt][nt][0], acc[mt][nt][1]);
            float2 v1 = make_float2(acc[mt][nt][2], acc[mt][nt][3]);
            if (HAS_BIAS) {
                float2 b = *reinterpret_cast<const float2*>(bias + col);
                v0.x += b.x; v0.y += b.y;
                v1.x += b.x; v1.y += b.y;
            }
            *reinterpret_cast<float2*>(C + (size_t)row * ldc + col) = v0;
            *reinterpret_cast<float2*>(C + (size_t)(row + 8) * ldc + col) = v1;
        }
    }
}

extern "C" void kernel_launch(void* const* d_in, const int* in_sizes, int n_in,
                              void* d_out, int out_size)
{
    const float* x    = (const float*)d_in[0];   // [8192,4096]
    const float* U    = (const float*)d_in[1];   // [4096,1024]
    const float* S    = (const float*)d_in[2];   // [1024]
    const float* V    = (const float*)d_in[3];   // [4096,1024]
    const float* bias = (const float*)d_in[4];   // [4096]
    float* out = (float*)d_out;                  // [8192,4096]

    float* Vt = nullptr; float* Ts = nullptr;
    cudaGetSymbolAddress((void**)&Vt, g_Vt);
    cudaGetSymbolAddress((void**)&Ts, g_Ts);

    cudaFuncSetAttribute(tf32_gemm_nt<false>,
                         cudaFuncAttributeMaxDynamicSharedMemorySize, SMEM_TOTAL);
    cudaFuncSetAttribute(tf32_gemm_nt<true>,
                         cudaFuncAttributeMaxDynamicSharedMemorySize, SMEM_TOTAL);

    // prep: Vt = (V*S)^T  [1024,4096]
    prep_vt<<<dim3(128, 32), dim3(32, 8)>>>(V, S, Vt);

    // GEMM1: Ts = x @ Vt^T   (M=8192, N=1024, K=4096)
    tf32_gemm_nt<false><<<dim3(1024 / CTA_N, 8192 / CTA_M), 256, SMEM_TOTAL>>>(
        x, Vt, nullptr, Ts, 4096, 4096, 4096, 1024);

    // GEMM2: out = Ts @ U^T + bias   (M=8192, N=4096, K=1024)
    tf32_gemm_nt<true><<<dim3(4096 / CTA_N, 8192 / CTA_M), 256, SMEM_TOTAL>>>(
        Ts, U, bias, out, 1024, 1024, 1024, 4096);
}

// round 4
// speedup vs baseline: 5.2892x; 1.6160x over previous
#include <cuda_runtime.h>
#include <cuda_fp16.h>
#include <cstdint>

// out = x @ V @ diag(S) @ U^T + bias  via mma.sync m16n8k16 fp16 (f32 accum).
// fp16 has the same 10-bit mantissa as tf32; all operand magnitudes fit range.
// GEMM1 (NT): Ts[8192,1024] = xh[8192,4096] @ Vth[1024,4096]^T   (Ts stored fp16)
// GEMM2 (NT): out[8192,4096] = Ts[8192,1024] @ Uh[4096,1024]^T + bias
// All operands pre-converted to fp16 so GEMM loaders are pure copies (no cvt).

#define CTA_M 128
#define CTA_N 128
#define CTA_K 32

// Fragment-ordered smem blocks (one m16k16 / n8k16 fp16 mma tile each), padded.
static constexpr int A_BLK = 528;   // 512B payload (32 lanes x 16B)
static constexpr int B_BLK = 272;   // 256B payload (32 lanes x 8B)
static constexpr int A_STAGE = 8 * 2 * A_BLK;    // 8 mtiles * 2 ktiles = 8448
static constexpr int B_STAGE = 16 * 2 * B_BLK;   // 16 ntiles * 2 ktiles = 8704
static constexpr int SMEM_TOTAL = 2 * (A_STAGE + B_STAGE);  // 34304 B

// Scratch (allocation-free rule: __device__ globals)
__device__ __align__(128) __half g_xh[8192 * 4096];   // x in fp16
__device__ __align__(128) __half g_Vth[1024 * 4096];  // (V*S)^T in fp16
__device__ __align__(128) __half g_Uh[4096 * 1024];   // U in fp16
__device__ __align__(128) __half g_Ts[8192 * 1024];   // intermediate in fp16

__device__ __forceinline__ void mma_f16(float& d0, float& d1, float& d2, float& d3,
                                        uint32_t a0, uint32_t a1, uint32_t a2, uint32_t a3,
                                        uint32_t b0, uint32_t b1) {
    asm volatile(
        "mma.sync.aligned.m16n8k16.row.col.f32.f16.f16.f32 "
        "{%0,%1,%2,%3}, {%4,%5,%6,%7}, {%8,%9}, {%0,%1,%2,%3};"
        : "+f"(d0), "+f"(d1), "+f"(d2), "+f"(d3)
        : "r"(a0), "r"(a1), "r"(a2), "r"(a3), "r"(b0), "r"(b1));
}

// ---------------- prep kernels ----------------
__global__ void cvt_f2h(const float* __restrict__ in, __half* __restrict__ out, int n4) {
    int i = blockIdx.x * blockDim.x + threadIdx.x;
    if (i < n4) {
        float4 v = *reinterpret_cast<const float4*>(in + (size_t)i * 4);
        __half2 h0 = __floats2half2_rn(v.x, v.y);
        __half2 h1 = __floats2half2_rn(v.z, v.w);
        uint2 o = make_uint2(*(uint32_t*)&h0, *(uint32_t*)&h1);
        *reinterpret_cast<uint2*>(out + (size_t)i * 4) = o;
    }
}

__global__ void prep_vt_h(const float* __restrict__ V, const float* __restrict__ S,
                          __half* __restrict__ Vt) {
    __shared__ float t[32][33];
    int k0 = blockIdx.x * 32;   // over 4096
    int n0 = blockIdx.y * 32;   // over 1024
    int tx = threadIdx.x, ty = threadIdx.y;
    #pragma unroll
    for (int r = ty; r < 32; r += 8)
        t[r][tx] = V[(size_t)(k0 + r) * 1024 + n0 + tx];
    __syncthreads();
    #pragma unroll
    for (int r = ty; r < 32; r += 8) {
        int n = n0 + r, k = k0 + tx;
        Vt[(size_t)n * 4096 + k] = __float2half_rn(t[tx][r] * S[n]);
    }
}

// ---------------- main NT GEMM: C[M,N] = A[M,K] @ B[N,K]^T ----------------
// EPI_HALF: C is fp16 (GEMM1 -> Ts). Else C is f32 with +bias (GEMM2).
template <bool EPI_HALF>
__global__ __launch_bounds__(128, 2) void fp16_gemm_nt(
    const __half* __restrict__ A, const __half* __restrict__ B,
    const float* __restrict__ bias, void* __restrict__ Cv,
    int K, int lda, int ldb, int ldc)
{
    extern __shared__ char sm[];
    const int tid = threadIdx.x;
    const int bm = blockIdx.y * CTA_M;
    const int bn = blockIdx.x * CTA_N;

    // 4 warps as 2(m) x 2(n); warp tile 64x64
    const int wid = tid >> 5, lane = tid & 31;
    const int wm = wid >> 1, wn = wid & 1;

    // ---- loader decomposition ----
    // uint4 (8 halves) index u = tid + 128*j: row = row0 + 32*j, k-chunk c8 fixed
    const int row0 = tid >> 2;          // 0..31
    const int c8 = (tid & 3) * 8;       // 0,8,16,24
    const int kt = c8 >> 4;             // ktile 0/1
    const int cc = c8 & 15;             // 0 or 8 within k16
    const int laneS = (row0 & 7) * 4;   // lane slot base (row&7 invariant under +32j)
    const int regA = ((row0 >> 3) & 1) | ((cc >> 3) << 1);
    const int regB = cc >> 3;
    const int mt0 = row0 >> 4;          // +2 per j
    const int nt0 = row0 >> 3;          // +4 per j

    auto As = [&](int p) { return p * A_STAGE; };
    auto Bs = [&](int p) { return 2 * A_STAGE + p * B_STAGE; };

    uint4 va[4], vb[4];

    auto ldg = [&](int tc) {
        const int k0 = tc * CTA_K + c8;
        #pragma unroll
        for (int j = 0; j < 4; j++) {
            va[j] = *reinterpret_cast<const uint4*>(A + (size_t)(bm + row0 + 32 * j) * lda + k0);
            vb[j] = *reinterpret_cast<const uint4*>(B + (size_t)(bn + row0 + 32 * j) * ldb + k0);
        }
    };

    auto sts = [&](int p) {
        #pragma unroll
        for (int j = 0; j < 4; j++) {
            const uint32_t* pa = &va[j].x;
            const uint32_t* pb = &vb[j].x;
            int ablk = As(p) + ((mt0 + 2 * j) * 2 + kt) * A_BLK;
            int bblk = Bs(p) + ((nt0 + 4 * j) * 2 + kt) * B_BLK;
            #pragma unroll
            for (int e = 0; e < 4; e++) {
                *reinterpret_cast<uint32_t*>(sm + ablk + (laneS + e) * 16 + regA * 4) = pa[e];
                *reinterpret_cast<uint32_t*>(sm + bblk + (laneS + e) * 8 + regB * 4) = pb[e];
            }
        }
    };

    float acc[4][8][4];
    #pragma unroll
    for (int i = 0; i < 4; i++)
        #pragma unroll
        for (int j = 0; j < 8; j++)
            #pragma unroll
            for (int r = 0; r < 4; r++)
                acc[i][j][r] = 0.0f;

    const int T = K / CTA_K;
    ldg(0);
    sts(0);
    __syncthreads();

    for (int tc = 0; tc < T; ++tc) {
        const int p = tc & 1;
        if (tc + 1 < T) ldg(tc + 1);

        #pragma unroll
        for (int ks = 0; ks < 2; ks++) {
            uint4 af[4];
            uint2 bf[8];
            #pragma unroll
            for (int mt = 0; mt < 4; mt++)
                af[mt] = *reinterpret_cast<const uint4*>(
                    sm + As(p) + ((wm * 4 + mt) * 2 + ks) * A_BLK + lane * 16);
            #pragma unroll
            for (int nt = 0; nt < 8; nt++)
                bf[nt] = *reinterpret_cast<const uint2*>(
                    sm + Bs(p) + ((wn * 8 + nt) * 2 + ks) * B_BLK + lane * 8);
            #pragma unroll
            for (int mt = 0; mt < 4; mt++)
                #pragma unroll
                for (int nt = 0; nt < 8; nt++)
                    mma_f16(acc[mt][nt][0], acc[mt][nt][1], acc[mt][nt][2], acc[mt][nt][3],
                            af[mt].x, af[mt].y, af[mt].z, af[mt].w,
                            bf[nt].x, bf[nt].y);
        }

        if (tc + 1 < T) sts((tc + 1) & 1);
        __syncthreads();
    }

    // ---- epilogue ----
    const int g = lane >> 2, tig = lane & 3;
    #pragma unroll
    for (int mt = 0; mt < 4; mt++) {
        #pragma unroll
        for (int nt = 0; nt < 8; nt++) {
            int row = bm + wm * 64 + mt * 16 + g;
            int col = bn + wn * 64 + nt * 8 + tig * 2;
            if (EPI_HALF) {
                __half* C = (__half*)Cv;
                __half2 h0 = __floats2half2_rn(acc[mt][nt][0], acc[mt][nt][1]);
                __half2 h1 = __floats2half2_rn(acc[mt][nt][2], acc[mt][nt][3]);
                *reinterpret_cast<__half2*>(C + (size_t)row * ldc + col) = h0;
                *reinterpret_cast<__half2*>(C + (size_t)(row + 8) * ldc + col) = h1;
            } else {
                float* C = (float*)Cv;
                float2 b = *reinterpret_cast<const float2*>(bias + col);
                float2 v0 = make_float2(acc[mt][nt][0] + b.x, acc[mt][nt][1] + b.y);
                float2 v1 = make_float2(acc[mt][nt][2] + b.x, acc[mt][nt][3] + b.y);
                *reinterpret_cast<float2*>(C + (size_t)row * ldc + col) = v0;
                *reinterpret_cast<float2*>(C + (size_t)(row + 8) * ldc + col) = v1;
            }
        }
    }
}

extern "C" void kernel_launch(void* const* d_in, const int* in_sizes, int n_in,
                              void* d_out, int out_size)
{
    const float* x    = (const float*)d_in[0];   // [8192,4096]
    const float* U    = (const float*)d_in[1];   // [4096,1024]
    const float* S    = (const float*)d_in[2];   // [1024]
    const float* V    = (const float*)d_in[3];   // [4096,1024]
    const float* bias = (const float*)d_in[4];   // [4096]
    float* out = (float*)d_out;                  // [8192,4096]

    __half *xh = nullptr, *Vth = nullptr, *Uh = nullptr, *Ts = nullptr;
    cudaGetSymbolAddress((void**)&xh, g_xh);
    cudaGetSymbolAddress((void**)&Vth, g_Vth);
    cudaGetSymbolAddress((void**)&Uh, g_Uh);
    cudaGetSymbolAddress((void**)&Ts, g_Ts);

    cudaFuncSetAttribute(fp16_gemm_nt<true>,
                         cudaFuncAttributeMaxDynamicSharedMemorySize, SMEM_TOTAL);
    cudaFuncSetAttribute(fp16_gemm_nt<false>,
                         cudaFuncAttributeMaxDynamicSharedMemorySize, SMEM_TOTAL);

    // prep: x -> fp16, U -> fp16, Vt = (V*S)^T -> fp16
    {
        int n4 = (8192 * 4096) / 4;
        cvt_f2h<<<(n4 + 255) / 256, 256>>>(x, xh, n4);
    }
    {
        int n4 = (4096 * 1024) / 4;
        cvt_f2h<<<(n4 + 255) / 256, 256>>>(U, Uh, n4);
    }
    prep_vt_h<<<dim3(128, 32), dim3(32, 8)>>>(V, S, Vth);

    // GEMM1: Ts = xh @ Vth^T   (M=8192, N=1024, K=4096), fp16 epilogue
    fp16_gemm_nt<true><<<dim3(1024 / CTA_N, 8192 / CTA_M), 128, SMEM_TOTAL>>>(
        xh, Vth, nullptr, Ts, 4096, 4096, 4096, 1024);

    // GEMM2: out = Ts @ Uh^T + bias   (M=8192, N=4096, K=1024), f32 epilogue
    fp16_gemm_nt<false><<<dim3(4096 / CTA_N, 8192 / CTA_M), 128, SMEM_TOTAL>>>(
        Ts, Uh, bias, out, 1024, 1024, 1024, 4096);
}